// round 15
// baseline (speedup 1.0000x reference)
#include <cuda_runtime.h>
#include <cstdint>

// MPJRDLayer fused forward — single launch: streaming blocks + one spinner
// finalize block, synced via release-RED / acquire-load on a completion counter.
// x:     [B=128, N=1024, D=8, S=64] fp32 (512 contiguous floats per (b,n))
// W:     [1024, 512] fp32;  theta, r_hat: [1024]
// out:   spikes [B*N] ++ rates [N] ++ thetas [N] ++ r_hats [N]

#define NB      128
#define NN      1024
#define DS      512
#define SBLOCKS 8192
#define NWARPS  (SBLOCKS * 8)   // 65536 streaming warps

__device__ float        g_cnt[NN];   // zero at load; reset by finalizer each call
__device__ unsigned int g_done;      // zero at load; reset by finalizer each call

__global__ __launch_bounds__(256)
void mpjrd_kernel(const float* __restrict__ x,
                  const float* __restrict__ W,
                  const float* __restrict__ theta,
                  const float* __restrict__ r_hat,
                  float* __restrict__ out)
{
    // ── Finalizer block: scheduled last, waits for all streaming warps ──
    if (blockIdx.x == SBLOCKS) {
        if (threadIdx.x == 0) {
            unsigned int v;
            do {
                asm volatile("ld.acquire.gpu.global.u32 %0, [%1];"
                             : "=r"(v) : "l"(&g_done));
                if (v != (unsigned)NWARPS) __nanosleep(200);
            } while (v != (unsigned)NWARPS);
        }
        __syncthreads();

        #pragma unroll
        for (int k = 0; k < 4; ++k) {
            const int n = k * 256 + threadIdx.x;
            const float c = g_cnt[n];
            g_cnt[n] = 0.0f;                      // replay-safe reset
            const float rate = c * (1.0f / 128.0f);
            const float rh   = 0.95f * __ldg(r_hat + n) + 0.05f * rate;
            const float thn  = __ldg(theta + n) + 0.1f * (rh - 0.1f);
            out[NB * NN + n]          = rate;
            out[NB * NN + NN + n]     = thn;
            out[NB * NN + 2 * NN + n] = rh;
        }
        __syncthreads();
        if (threadIdx.x == 0) g_done = 0u;        // replay-safe reset
        return;
    }

    // ── Streaming blocks: one warp per (n, b-pair) — unchanged R3 core ──
    const int warp = threadIdx.x >> 5;
    const int lane = threadIdx.x & 31;
    const int id   = blockIdx.x * 8 + warp;      // 0 .. 65535
    const int n    = id & (NN - 1);
    const int b0   = (id >> 10) << 1;            // 0,2,...,126
    const int b1   = b0 + 1;

    const float4* Wv = reinterpret_cast<const float4*>(W + (size_t)n * DS);
    const float4 w0 = Wv[0 * 32 + lane];
    const float4 w1 = Wv[1 * 32 + lane];
    const float4 w2 = Wv[2 * 32 + lane];
    const float4 w3 = Wv[3 * 32 + lane];

    const float4* xa = reinterpret_cast<const float4*>(x + ((size_t)b0 * NN + n) * DS);
    const float4* xb = reinterpret_cast<const float4*>(x + ((size_t)b1 * NN + n) * DS);

    const float4 a0 = xa[0 * 32 + lane];
    const float4 a1 = xa[1 * 32 + lane];
    const float4 a2 = xa[2 * 32 + lane];
    const float4 a3 = xa[3 * 32 + lane];
    const float4 c0 = xb[0 * 32 + lane];
    const float4 c1 = xb[1 * 32 + lane];
    const float4 c2 = xb[2 * 32 + lane];
    const float4 c3 = xb[3 * 32 + lane];

    float accA = 0.0f, accB = 0.0f;
    accA = fmaf(a0.x, w0.x, accA); accA = fmaf(a0.y, w0.y, accA);
    accA = fmaf(a0.z, w0.z, accA); accA = fmaf(a0.w, w0.w, accA);
    accA = fmaf(a1.x, w1.x, accA); accA = fmaf(a1.y, w1.y, accA);
    accA = fmaf(a1.z, w1.z, accA); accA = fmaf(a1.w, w1.w, accA);
    accA = fmaf(a2.x, w2.x, accA); accA = fmaf(a2.y, w2.y, accA);
    accA = fmaf(a2.z, w2.z, accA); accA = fmaf(a2.w, w2.w, accA);
    accA = fmaf(a3.x, w3.x, accA); accA = fmaf(a3.y, w3.y, accA);
    accA = fmaf(a3.z, w3.z, accA); accA = fmaf(a3.w, w3.w, accA);

    accB = fmaf(c0.x, w0.x, accB); accB = fmaf(c0.y, w0.y, accB);
    accB = fmaf(c0.z, w0.z, accB); accB = fmaf(c0.w, w0.w, accB);
    accB = fmaf(c1.x, w1.x, accB); accB = fmaf(c1.y, w1.y, accB);
    accB = fmaf(c1.z, w1.z, accB); accB = fmaf(c1.w, w1.w, accB);
    accB = fmaf(c2.x, w2.x, accB); accB = fmaf(c2.y, w2.y, accB);
    accB = fmaf(c2.z, w2.z, accB); accB = fmaf(c2.w, w2.w, accB);
    accB = fmaf(c3.x, w3.x, accB); accB = fmaf(c3.y, w3.y, accB);
    accB = fmaf(c3.z, w3.z, accB); accB = fmaf(c3.w, w3.w, accB);

    #pragma unroll
    for (int off = 16; off; off >>= 1) {
        accA += __shfl_xor_sync(0xFFFFFFFFu, accA, off);
        accB += __shfl_xor_sync(0xFFFFFFFFu, accB, off);
    }

    if (lane == 0) {
        const float th = theta[n];
        const float sA = (accA >= th) ? 1.0f : 0.0f;
        const float sB = (accB >= th) ? 1.0f : 0.0f;
        out[(size_t)b0 * NN + n] = sA;
        out[(size_t)b1 * NN + n] = sB;
        const float s = sA + sB;
        if (s != 0.0f) atomicAdd(&g_cnt[n], s);   // integer-valued: order-invariant

        // Fire-and-forget completion signal; release orders the g_cnt add.
        asm volatile("red.release.gpu.global.add.u32 [%0], %1;"
                     :: "l"(&g_done), "r"(1u) : "memory");
    }
}

extern "C" void kernel_launch(void* const* d_in, const int* in_sizes, int n_in,
                              void* d_out, int out_size)
{
    const float* x     = (const float*)d_in[0];
    const float* W     = (const float*)d_in[1];
    const float* theta = (const float*)d_in[2];
    const float* r_hat = (const float*)d_in[3];
    float* out = (float*)d_out;

    mpjrd_kernel<<<SBLOCKS + 1, 256>>>(x, W, theta, r_hat, out);
}